// round 17
// baseline (speedup 1.0000x reference)
#include <cuda_runtime.h>
#include <stdint.h>

#define D_EMB   512
#define H_NUM   8
#define T_STEPS 16
#define NB      2
#define SEQ     512
#define HD      64
#define M_ROWS  (NB * T_STEPS * SEQ)      // 16384
#define PBATCH  (NB * T_STEPS * H_NUM)    // 256

// ---- scratch ----
__device__ float g_Q[(size_t)M_ROWS * D_EMB];
__device__ float g_K[(size_t)M_ROWS * D_EMB];
__device__ float g_V[(size_t)M_ROWS * D_EMB];
__device__ float g_att[(size_t)M_ROWS * D_EMB];

// ---- helpers ----
__device__ __forceinline__ uint32_t f2tf(float x) {
    uint32_t r;
    asm("cvt.rna.tf32.f32 %0, %1;" : "=r"(r) : "f"(x));
    return r;
}
__device__ __forceinline__ void mma8(float* c, const uint32_t* a, uint32_t b0, uint32_t b1) {
    asm volatile(
        "mma.sync.aligned.m16n8k8.row.col.f32.tf32.tf32.f32 "
        "{%0,%1,%2,%3}, {%4,%5,%6,%7}, {%8,%9}, {%0,%1,%2,%3};"
        : "+f"(c[0]), "+f"(c[1]), "+f"(c[2]), "+f"(c[3])
        : "r"(a[0]), "r"(a[1]), "r"(a[2]), "r"(a[3]), "r"(b0), "r"(b1));
}
__device__ __forceinline__ void cpa16(uint32_t dst, const void* src) {
    asm volatile("cp.async.ca.shared.global [%0], [%1], 16;" :: "r"(dst), "l"(src));
}
__device__ __forceinline__ void cpa_commit() { asm volatile("cp.async.commit_group;"); }
__device__ __forceinline__ void cpa_wait1() { asm volatile("cp.async.wait_group 1;"); }
__device__ __forceinline__ void cpa_wait0() { asm volatile("cp.async.wait_group 0;"); }

// ============================================================================
// projection GEMM body (device-inlined, RAWA compile-time inside ONE global):
// 3-stage rotation, one barrier per stage:
//   wait(st) -> sync -> issue st+2 into stage (st+2)%3 -> compute stage st%3
// RAWA=1: A already tf32-rounded -> raw loads, no A-side cvt.
// roundC!=0: tf32-round outputs.
// smem: A 3x[128][36] + W 3x[32][136] = 107520 B (2 blocks/SM).
// ============================================================================
#define PJ_AS_W 4608
#define PJ_WS_W 4352
#define PJ_SMEM 107520

template<int RAWA>
__device__ __forceinline__ void proj_body(
    const float* __restrict__ A, const float* __restrict__ W,
    const float* __restrict__ bias, float* __restrict__ C,
    int roundC, unsigned char* smraw, int rowBlk, int colBlk)
{
    float* As = (float*)smraw;                         // [3][128][36]
    float* Ws = (float*)(smraw + 3 * PJ_AS_W * 4);     // [3][32][136]
    const uint32_t sAs = (uint32_t)__cvta_generic_to_shared(As);
    const uint32_t sWs = (uint32_t)__cvta_generic_to_shared(Ws);

    const int tid = threadIdx.x;
    const int lane = tid & 31, warp = tid >> 5;
    const int g = lane >> 2, t = lane & 3;
    const int wm = (warp >> 1) * 32;
    const int wn = (warp & 1) * 64;

    auto issue = [&](int st) {
        const int buf = st % 3;
        const int k0 = st * 32;
#pragma unroll
        for (int i = 0; i < 4; i++) {
            int seg = i * 256 + tid;
            int r = seg >> 3, s = (seg & 7) << 2;
            cpa16(sAs + ((buf * PJ_AS_W + r * 36 + s) << 2),
                  A + (size_t)(rowBlk + r) * 512 + k0 + s);
        }
#pragma unroll
        for (int i = 0; i < 4; i++) {
            int seg = i * 256 + tid;
            int kr = seg >> 5, s = (seg & 31) << 2;
            cpa16(sWs + ((buf * PJ_WS_W + kr * 136 + s) << 2),
                  W + (size_t)(k0 + kr) * 512 + colBlk + s);
        }
        cpa_commit();
    };

    float acc[2][8][4] = {};
    issue(0);
    issue(1);
    for (int st = 0; st < 16; st++) {
        if (st < 15) cpa_wait1(); else cpa_wait0();  // stage st landed
        __syncthreads();                             // publish st; retire refill target reads
        if (st + 2 < 16) issue(st + 2);
        const float* Ab = As + (st % 3) * PJ_AS_W;
        const float* Wb = Ws + (st % 3) * PJ_WS_W;
        const uint32_t* Au = (const uint32_t*)Ab;
#pragma unroll
        for (int ks = 0; ks < 4; ks++) {
            const int kc = ks * 8 + t;
            uint32_t a[2][4];
#pragma unroll
            for (int mi = 0; mi < 2; mi++) {
                const int m = wm + mi * 16 + g;
                if (RAWA) {
                    a[mi][0] = Au[m * 36 + kc];
                    a[mi][1] = Au[(m + 8) * 36 + kc];
                    a[mi][2] = Au[m * 36 + kc + 4];
                    a[mi][3] = Au[(m + 8) * 36 + kc + 4];
                } else {
                    a[mi][0] = f2tf(Ab[m * 36 + kc]);
                    a[mi][1] = f2tf(Ab[(m + 8) * 36 + kc]);
                    a[mi][2] = f2tf(Ab[m * 36 + kc + 4]);
                    a[mi][3] = f2tf(Ab[(m + 8) * 36 + kc + 4]);
                }
            }
#pragma unroll
            for (int ni = 0; ni < 8; ni++) {
                const int n = wn + ni * 8 + g;
                uint32_t b0 = f2tf(Wb[kc * 136 + n]);
                uint32_t b1 = f2tf(Wb[(kc + 4) * 136 + n]);
                mma8(acc[0][ni], a[0], b0, b1);
                mma8(acc[1][ni], a[1], b0, b1);
            }
        }
    }
    __syncthreads();
#pragma unroll
    for (int mi = 0; mi < 2; mi++)
#pragma unroll
        for (int ni = 0; ni < 8; ni++) {
            const int col = colBlk + wn + ni * 8 + 2 * t;
            const float bx = bias[col], by = bias[col + 1];
            const int r0 = rowBlk + wm + mi * 16 + g;
            float2 v0 = {acc[mi][ni][0] + bx, acc[mi][ni][1] + by};
            float2 v1 = {acc[mi][ni][2] + bx, acc[mi][ni][3] + by};
            if (roundC) {
                v0.x = __uint_as_float(f2tf(v0.x)); v0.y = __uint_as_float(f2tf(v0.y));
                v1.x = __uint_as_float(f2tf(v1.x)); v1.y = __uint_as_float(f2tf(v1.y));
            }
            *(float2*)(C + (size_t)r0 * 512 + col) = v0;
            *(float2*)(C + (size_t)(r0 + 8) * 512 + col) = v1;
        }
}

// single global symbol; runtime rawA dispatches to the compile-time body
__global__ __launch_bounds__(256, 2) void proj3_gemm(
    const float* __restrict__ A0, const float* __restrict__ W0,
    const float* __restrict__ B0, float* __restrict__ C0,
    const float* __restrict__ A1, const float* __restrict__ W1,
    const float* __restrict__ B1, float* __restrict__ C1,
    const float* __restrict__ A2, const float* __restrict__ W2,
    const float* __restrict__ B2, float* __restrict__ C2,
    int roundC, int rawA)
{
    const int z = blockIdx.z;
    const float* A    = (z == 0) ? A0 : (z == 1) ? A1 : A2;
    const float* W    = (z == 0) ? W0 : (z == 1) ? W1 : W2;
    const float* bias = (z == 0) ? B0 : (z == 1) ? B1 : B2;
    float*       C    = (z == 0) ? C0 : (z == 1) ? C1 : C2;

    extern __shared__ __align__(16) unsigned char smraw[];
    const int rowBlk = blockIdx.y * 128;
    const int colBlk = blockIdx.x * 128;

    if (rawA) proj_body<1>(A, W, bias, C, roundC, smraw, rowBlk, colBlk);
    else      proj_body<0>(A, W, bias, C, roundC, smraw, rowBlk, colBlk);
}

// ============================================================================
// fused attention (R15 form): register-resident scores, raw tf32 loads,
// 3-stage K/V rotation, 1 barrier/chunk. Epilogue tf32-rounds g_att.
// ============================================================================
#define FA_QK_W  68
#define FA_V_W   72
#define FA_KBUF  (64 * FA_QK_W)
#define FA_VBUF  (64 * FA_V_W)
#define FA_QOFF  0
#define FA_KOFF  17408
#define FA_VOFF  69632
#define FA_STAT  124928
#define FA_SMEM  125952
__global__ __launch_bounds__(512, 1) void fused_attn(
    const float* __restrict__ mw, const float* __restrict__ tsync,
    const int* __restrict__ qm, const int* __restrict__ km)
{
    extern __shared__ __align__(16) unsigned char smraw[];
    uint32_t* Qs    = (uint32_t*)(smraw + FA_QOFF);   // [64][68]
    uint32_t* Ks    = (uint32_t*)(smraw + FA_KOFF);   // [3][64][68]
    uint32_t* Vs    = (uint32_t*)(smraw + FA_VOFF);   // [3][64][72]
    float*    stats = (float*)(smraw + FA_STAT);      // [64][4]
    float*    Opart = (float*)smraw;                  // [16][16][68] overlay
    const uint32_t sQ = (uint32_t)__cvta_generic_to_shared(Qs);
    const uint32_t sK = (uint32_t)__cvta_generic_to_shared(Ks);
    const uint32_t sV = (uint32_t)__cvta_generic_to_shared(Vs);

    const int tid = threadIdx.x;
    const int lane = tid & 31, warp = tid >> 5;
    const int g = lane >> 2, t = lane & 3;
    const int wm = (warp >> 2) * 16;
    const int wni = warp & 3;
    const int wn = wni * 16;
    const int sig = (g >> 1) + ((g & 1) << 2);

    const int tile = blockIdx.x;
    const int p = blockIdx.y;
    const int h = p & 7;
    const int tt = (p >> 3) & 15;
    const int b = p >> 7;
    const size_t rowbase = ((size_t)(b * T_STEPS + tt) * SEQ);
    const float* Qg = g_Q + (rowbase + tile * 64) * 512 + h * HD;
    const float* Kg = g_K + rowbase * 512 + h * HD;
    const float* Vg = g_V + rowbase * 512 + h * HD;
    float*       Cg = g_att + (rowbase + tile * 64) * 512 + h * HD;

    const float alpha = 0.125f * mw[qm[0] * H_NUM + h] * mw[km[0] * H_NUM + h];
    const float sy = tsync[tt * H_NUM + h];

    auto issueK = [&](int ci, int stage) {
#pragma unroll
        for (int i = 0; i < 2; i++) {
            int seg = i * 512 + tid;
            int r = seg >> 4, s4 = (seg & 15) << 2;
            cpa16(sK + ((stage * FA_KBUF + r * FA_QK_W + s4) << 2),
                  Kg + (size_t)(ci * 64 + r) * 512 + s4);
        }
        cpa_commit();
    };
    auto issueV = [&](int ci, int stage) {
#pragma unroll
        for (int i = 0; i < 2; i++) {
            int seg = i * 512 + tid;
            int r = seg >> 4, s4 = (seg & 15) << 2;
            cpa16(sV + ((stage * FA_VBUF + r * FA_V_W + s4) << 2),
                  Vg + (size_t)(ci * 64 + r) * 512 + s4);
        }
        cpa_commit();
    };

    // ---- prologue: {Q + K0} group, {K1} group ----
#pragma unroll
    for (int i = 0; i < 2; i++) {
        int seg = i * 512 + tid;
        int r = seg >> 4, s4 = (seg & 15) << 2;
        cpa16(sQ + ((r * FA_QK_W + s4) << 2), Qg + (size_t)r * 512 + s4);
        cpa16(sK + ((r * FA_QK_W + s4) << 2), Kg + (size_t)r * 512 + s4);
    }
    cpa_commit();
    issueK(1, 1);
    cpa_wait1();
    __syncthreads();

    // ---- preload Q a-fragments (raw: pre-rounded) ----
    uint32_t Qf[8][4];
#pragma unroll
    for (int ks = 0; ks < 8; ks++) {
        const int kc = ks * 8 + t;
        Qf[ks][0] = Qs[(wm + g) * FA_QK_W + kc];
        Qf[ks][1] = Qs[(wm + 8 + g) * FA_QK_W + kc];
        Qf[ks][2] = Qs[(wm + g) * FA_QK_W + kc + 4];
        Qf[ks][3] = Qs[(wm + 8 + g) * FA_QK_W + kc + 4];
    }

    // ---- phase 1: scores into registers ----
    float accS[8][2][4] = {};
#pragma unroll
    for (int c = 0; c < 8; c++) {
        if (c < 7) cpa_wait1(); else cpa_wait0();
        __syncthreads();
        if (c + 2 < 8) issueK(c + 2, (c + 2) % 3);
        const uint32_t* Kb = Ks + (c % 3) * FA_KBUF;
#pragma unroll
        for (int ks = 0; ks < 8; ks++) {
            const int kc = ks * 8 + t;
#pragma unroll
            for (int kt = 0; kt < 2; kt++) {
                const int n = wn + kt * 8 + sig;
                uint32_t b0 = Kb[n * FA_QK_W + kc];
                uint32_t b1 = Kb[n * FA_QK_W + kc + 4];
                mma8(accS[c][kt], Qf[ks], b0, b1);
            }
        }
    }

    // ---- prefetch V chunks 0,1 ----
    issueV(0, 0);
    issueV(1, 1);

    // ---- register softmax ----
    {
        float* aS = &accS[0][0][0];
#pragma unroll
        for (int i = 0; i < 64; i++) aS[i] = aS[i] * alpha + sy;

        float m0 = -1e30f, m1 = -1e30f;
#pragma unroll
        for (int i = 0; i < 64; i += 4) {
            m0 = fmaxf(m0, fmaxf(aS[i], aS[i + 1]));
            m1 = fmaxf(m1, fmaxf(aS[i + 2], aS[i + 3]));
        }
        m0 = fmaxf(m0, __shfl_xor_sync(0xFFFFFFFFu, m0, 1));
        m0 = fmaxf(m0, __shfl_xor_sync(0xFFFFFFFFu, m0, 2));
        m1 = fmaxf(m1, __shfl_xor_sync(0xFFFFFFFFu, m1, 1));
        m1 = fmaxf(m1, __shfl_xor_sync(0xFFFFFFFFu, m1, 2));
        if (t == 0) {
            stats[(wm + g) * 4 + wni] = m0;
            stats[(wm + 8 + g) * 4 + wni] = m1;
        }
        __syncthreads();
        {
            float4 v0 = *(float4*)&stats[(wm + g) * 4];
            m0 = fmaxf(fmaxf(v0.x, v0.y), fmaxf(v0.z, v0.w));
            float4 v1 = *(float4*)&stats[(wm + 8 + g) * 4];
            m1 = fmaxf(fmaxf(v1.x, v1.y), fmaxf(v1.z, v1.w));
        }
        __syncthreads();

        float s0 = 0.f, s1 = 0.f;
#pragma unroll
        for (int i = 0; i < 64; i += 4) {
            float p0 = 1.f / (1.f + __expf(-5.f * (aS[i]     - m0)));
            float p1 = 1.f / (1.f + __expf(-5.f * (aS[i + 1] - m0)));
            float p2 = 1.f / (1.f + __expf(-5.f * (aS[i + 2] - m1)));
            float p3 = 1.f / (1.f + __expf(-5.f * (aS[i + 3] - m1)));
            aS[i] = p0; aS[i + 1] = p1; aS[i + 2] = p2; aS[i + 3] = p3;
            s0 += p0 + p1; s1 += p2 + p3;
        }
        s0 += __shfl_xor_sync(0xFFFFFFFFu, s0, 1);
        s0 += __shfl_xor_sync(0xFFFFFFFFu, s0, 2);
        s1 += __shfl_xor_sync(0xFFFFFFFFu, s1, 1);
        s1 += __shfl_xor_sync(0xFFFFFFFFu, s1, 2);
        if (t == 0) {
            stats[(wm + g) * 4 + wni] = s0;
            stats[(wm + 8 + g) * 4 + wni] = s1;
        }
        __syncthreads();
        {
            float4 v0 = *(float4*)&stats[(wm + g) * 4];
            s0 = v0.x + v0.y + v0.z + v0.w;
            float4 v1 = *(float4*)&stats[(wm + 8 + g) * 4];
            s1 = v1.x + v1.y + v1.z + v1.w;
        }
        const float inv0 = 1.f / (s0 + 1e-8f);
        const float inv1 = 1.f / (s1 + 1e-8f);
#pragma unroll
        for (int i = 0; i < 64; i += 4) {
            aS[i]     = __uint_as_float(f2tf(aS[i]     * inv0));
            aS[i + 1] = __uint_as_float(f2tf(aS[i + 1] * inv0));
            aS[i + 2] = __uint_as_float(f2tf(aS[i + 2] * inv1));
            aS[i + 3] = __uint_as_float(f2tf(aS[i + 3] * inv1));
        }
    }

    // ---- phase 2: partial O (3-stage, 1 barrier/chunk) ----
    float acc2[8][4] = {};
#pragma unroll
    for (int c = 0; c < 8; c++) {
        if (c < 7) cpa_wait1(); else cpa_wait0();
        __syncthreads();
        if (c + 2 < 8) issueV(c + 2, (c + 2) % 3);
        const uint32_t* Vb = Vs + (c % 3) * FA_VBUF;
#pragma unroll
        for (int kt = 0; kt < 2; kt++) {
            uint32_t a[4];
            a[0] = __float_as_uint(accS[c][kt][0]);
            a[1] = __float_as_uint(accS[c][kt][2]);
            a[2] = __float_as_uint(accS[c][kt][1]);
            a[3] = __float_as_uint(accS[c][kt][3]);
            const int klb = wn + kt * 8 + t;
#pragma unroll
            for (int ci = 0; ci < 8; ci++) {
                const int n = ci * 8 + g;
                uint32_t b0 = Vb[klb * FA_V_W + n];
                uint32_t b1 = Vb[(klb + 4) * FA_V_W + n];
                mma8(acc2[ci], a, b0, b1);
            }
        }
    }

    // ---- epilogue: store partials, 4-way reduce, tf32-round, STG ----
    {
        const int opb = warp * 1088;
#pragma unroll
        for (int ci = 0; ci < 8; ci++) {
            float2 v0 = {acc2[ci][0], acc2[ci][1]};
            *(float2*)&Opart[opb + g * FA_QK_W + ci * 8 + 2 * t] = v0;
            float2 v1 = {acc2[ci][2], acc2[ci][3]};
            *(float2*)&Opart[opb + (g + 8) * FA_QK_W + ci * 8 + 2 * t] = v1;
        }
    }
    __syncthreads();
    {
        const int rr = tid >> 3;
        const int c8 = (tid & 7) * 8;
        float4 o0 = {0.f, 0.f, 0.f, 0.f}, o1 = {0.f, 0.f, 0.f, 0.f};
#pragma unroll
        for (int wv = 0; wv < 4; wv++) {
            const float* src = Opart + ((rr >> 4) * 4 + wv) * 1088
                             + (rr & 15) * FA_QK_W + c8;
            float4 x0 = *(const float4*)src;
            float4 x1 = *(const float4*)(src + 4);
            o0.x += x0.x; o0.y += x0.y; o0.z += x0.z; o0.w += x0.w;
            o1.x += x1.x; o1.y += x1.y; o1.z += x1.z; o1.w += x1.w;
        }
        // round to tf32 so the output projection can load raw (rawA=1)
        o0.x = __uint_as_float(f2tf(o0.x)); o0.y = __uint_as_float(f2tf(o0.y));
        o0.z = __uint_as_float(f2tf(o0.z)); o0.w = __uint_as_float(f2tf(o0.w));
        o1.x = __uint_as_float(f2tf(o1.x)); o1.y = __uint_as_float(f2tf(o1.y));
        o1.z = __uint_as_float(f2tf(o1.z)); o1.w = __uint_as_float(f2tf(o1.w));
        *(float4*)(Cg + (size_t)rr * 512 + c8) = o0;
        *(float4*)(Cg + (size_t)rr * 512 + c8 + 4) = o1;
    }
}

// ============================================================================
// launch
// ============================================================================
extern "C" void kernel_launch(void* const* d_in, const int* in_sizes, int n_in,
                              void* d_out, int out_size)
{
    const float* q_sp = (const float*)d_in[0];
    const float* k_sp = (const float*)d_in[1];
    const float* v_sp = (const float*)d_in[2];
    const float* Wq = (const float*)d_in[3];  const float* bq = (const float*)d_in[4];
    const float* Wk = (const float*)d_in[5];  const float* bk = (const float*)d_in[6];
    const float* Wv = (const float*)d_in[7];  const float* bv = (const float*)d_in[8];
    const float* Wo = (const float*)d_in[9];  const float* bo = (const float*)d_in[10];
    const float* mw    = (const float*)d_in[11];
    const float* tsync = (const float*)d_in[12];
    const int* qm = (const int*)d_in[13];
    const int* km = (const int*)d_in[14];
    float* out = (float*)d_out;

    // unconditional (no static guards): idempotent, not stream-ordered
    cudaFuncSetAttribute(proj3_gemm, cudaFuncAttributeMaxDynamicSharedMemorySize, PJ_SMEM);
    cudaFuncSetAttribute(fused_attn, cudaFuncAttributeMaxDynamicSharedMemorySize, FA_SMEM);

    float *dQ, *dK, *dV, *dAtt;
    cudaGetSymbolAddress((void**)&dQ, g_Q);
    cudaGetSymbolAddress((void**)&dK, g_K);
    cudaGetSymbolAddress((void**)&dV, g_V);
    cudaGetSymbolAddress((void**)&dAtt, g_att);

    // Q, K, V projections (A raw -> cvt in loop; outputs tf32-rounded)
    proj3_gemm<<<dim3(D_EMB / 128, M_ROWS / 128, 3), 256, PJ_SMEM>>>(
        q_sp, Wq, bq, dQ,
        k_sp, Wk, bk, dK,
        v_sp, Wv, bv, dV, 1, 0);

    fused_attn<<<dim3(SEQ / 64, PBATCH), 512, FA_SMEM>>>(mw, tsync, qm, km);

    // output projection: g_att is tf32-pre-rounded -> rawA=1, full fp32 out
    proj3_gemm<<<dim3(D_EMB / 128, M_ROWS / 128, 1), 256, PJ_SMEM>>>(
        dAtt, Wo, bo, out,
        dAtt, Wo, bo, out,
        dAtt, Wo, bo, out, 0, 1);
}